// round 5
// baseline (speedup 1.0000x reference)
#include <cuda_runtime.h>

#define NB   32
#define T    131072
#define LCH  128
#define C    1024     // T / LCH
#define NSEC 5
#define NLEV 10       // log2(C)

// ---------------- scratch (device globals, no allocation) ----------------
__device__ float g_coef[NB][NSEC][5];      // B0,B1,B2,A1,A2 (normalized)
__device__ float g_P[NB][NLEV][100];       // A^(LCH*2^k), k=0..9 (double-computed)
__device__ float g_v[NB][C][10];           // zero-state chunk final states
__device__ float g_w[NB][C][10];           // true chunk initial states

__constant__ float c_lo[15] = {-12.f,  20.f, 0.1f, -12.f,   20.f, 0.1f,
                               -12.f, 200.f, 0.1f, -12.f, 2000.f, 0.1f,
                               -12.f,4000.f, 0.1f};
__constant__ float c_hi[15] = { 12.f,2000.f,10.f,  12.f,  200.f,10.f,
                                12.f,2000.f,10.f,  12.f,12000.f,10.f,
                                12.f,16000.f,10.f};

// ---------------- setup: coeffs + sos output + matrix powers (double) ----------------
__global__ void k_setup(const float* __restrict__ cp, float* __restrict__ sos_out) {
    int b = blockIdx.x, tid = threadIdx.x;
    __shared__ double sd[NSEC][5];
    __shared__ double Ma[100], Mb[100];

    if (tid < NSEC) {
        int k = tid;
        double pg = (double)c_lo[3*k+0] + (double)cp[b*15 + 3*k+0] * ((double)c_hi[3*k+0] - (double)c_lo[3*k+0]);
        double f0 = (double)c_lo[3*k+1] + (double)cp[b*15 + 3*k+1] * ((double)c_hi[3*k+1] - (double)c_lo[3*k+1]);
        double q  = (double)c_lo[3*k+2] + (double)cp[b*15 + 3*k+2] * ((double)c_hi[3*k+2] - (double)c_lo[3*k+2]);

        double A     = pow(10.0, pg / 40.0);
        double w0    = 2.0 * 3.14159265358979323846 * f0 / 44100.0;
        double alpha = sin(w0) / (2.0 * q);
        double cw    = cos(w0);
        double sA    = sqrt(A);
        double b0, b1, b2, a0, a1, a2;
        if (k == 0) {            // low shelf
            b0 = A*((A+1) - (A-1)*cw + 2*sA*alpha);
            b1 = 2*A*((A-1) - (A+1)*cw);
            b2 = A*((A+1) - (A-1)*cw - 2*sA*alpha);
            a0 = (A+1) + (A-1)*cw + 2*sA*alpha;
            a1 = -2*((A-1) + (A+1)*cw);
            a2 = (A+1) + (A-1)*cw - 2*sA*alpha;
        } else if (k == 4) {     // high shelf
            b0 = A*((A+1) + (A-1)*cw + 2*sA*alpha);
            b1 = -2*A*((A-1) + (A+1)*cw);
            b2 = A*((A+1) + (A-1)*cw - 2*sA*alpha);
            a0 = (A+1) - (A-1)*cw + 2*sA*alpha;
            a1 = 2*((A-1) - (A+1)*cw);
            a2 = (A+1) - (A-1)*cw - 2*sA*alpha;
        } else {                 // peaking
            b0 = 1 + alpha*A;  b1 = -2*cw;  b2 = 1 - alpha*A;
            a0 = 1 + alpha/A;  a1 = -2*cw;  a2 = 1 - alpha/A;
        }
        double B0 = b0/a0, B1 = b1/a0, B2 = b2/a0, A1 = a1/a0, A2 = a2/a0;
        sd[k][0]=B0; sd[k][1]=B1; sd[k][2]=B2; sd[k][3]=A1; sd[k][4]=A2;
        g_coef[b][k][0]=(float)B0; g_coef[b][k][1]=(float)B1; g_coef[b][k][2]=(float)B2;
        g_coef[b][k][3]=(float)A1; g_coef[b][k][4]=(float)A2;
        if (sos_out) {
            float* so = sos_out + b*30 + k*6;
            so[0]=(float)B0; so[1]=(float)B1; so[2]=(float)B2;
            so[3]=1.0f;      so[4]=(float)A1; so[5]=(float)A2;
        }
    }
    __syncthreads();

    // one-step state matrix A by basis simulation (double): column j = step(e_j, x=0)
    if (tid < 10) {
        double z1[5] = {0,0,0,0,0}, z2[5] = {0,0,0,0,0};
        if (tid < 5) z1[tid] = 1.0; else z2[tid-5] = 1.0;
        double s = 0.0;
        #pragma unroll
        for (int k = 0; k < 5; k++) {
            double y   = fma(sd[k][0], s, z1[k]);
            double nz1 = fma(sd[k][1], s, fma(-sd[k][3], y, z2[k]));
            double nz2 = fma(sd[k][2], s, -sd[k][4]*y);
            z1[k] = nz1; z2[k] = nz2; s = y;
        }
        #pragma unroll
        for (int r = 0; r < 5; r++) { Ma[r*10+tid] = z1[r]; Ma[(5+r)*10+tid] = z2[r]; }
    }
    __syncthreads();

    // 16 squarings in double: after sq squarings M = A^(2^sq).
    // LCH = 128 = 2^7 -> scan levels are A^(2^(7+d)), d=0..9 -> store sq=7..16.
    double* cur = Ma; double* nxt = Mb;
    for (int sq = 1; sq <= 16; sq++) {
        double acc = 0.0;
        if (tid < 100) {
            int r = tid / 10, c2 = tid % 10;
            #pragma unroll
            for (int k = 0; k < 10; k++)
                acc = fma(cur[r*10+k], cur[k*10+c2], acc);
        }
        __syncthreads();
        if (tid < 100) nxt[tid] = acc;
        __syncthreads();
        double* t2 = cur; cur = nxt; nxt = t2;
        if (sq >= 7 && tid < 100) g_P[b][sq-7][tid] = (float)cur[tid];
    }
}

// ---------------- cascade step ----------------
__device__ __forceinline__ float eq_step(const float cf[5][5], float z1[5], float z2[5], float s) {
    #pragma unroll
    for (int k = 0; k < 5; k++) {
        float y   = fmaf(cf[k][0], s, z1[k]);
        float nz1 = fmaf(cf[k][1], s, fmaf(-cf[k][3], y, z2[k]));
        z2[k]     = fmaf(cf[k][2], s, -cf[k][4]*y);
        z1[k] = nz1; s = y;
    }
    return s;
}

// ---------------- phase 1: zero-state chunk final states ----------------
__global__ void __launch_bounds__(128) k_phase1(const float* __restrict__ x) {
    int t = blockIdx.x * blockDim.x + threadIdx.x;
    int b = t >> 10;           // / C
    int c = t & (C - 1);
    float cf[5][5];
    #pragma unroll
    for (int k = 0; k < 5; k++)
        #pragma unroll
        for (int i = 0; i < 5; i++) cf[k][i] = g_coef[b][k][i];
    float z1[5] = {0,0,0,0,0}, z2[5] = {0,0,0,0,0};
    const float4* xp = (const float4*)(x + (size_t)b*T + (size_t)c*LCH);
    #pragma unroll 4
    for (int i = 0; i < LCH/4; i++) {
        float4 v = __ldg(xp + i);
        eq_step(cf, z1, z2, v.x);
        eq_step(cf, z1, z2, v.y);
        eq_step(cf, z1, z2, v.z);
        eq_step(cf, z1, z2, v.w);
    }
    #pragma unroll
    for (int k = 0; k < 5; k++) { g_v[b][c][k] = z1[k]; g_v[b][c][5+k] = z2[k]; }
}

// ---------------- inter-chunk Blelloch scan (one CTA per batch, work-efficient) ----------------
__global__ void __launch_bounds__(C) k_scan() {
    int b = blockIdx.x;
    int tid = threadIdx.x;     // C threads
    __shared__ float sd[C][11];      // padded: 2-way max bank conflicts
    __shared__ float Pk[NLEV][100];

    #pragma unroll
    for (int r = 0; r < 10; r++) sd[tid][r] = g_v[b][tid][r];
    for (int i = tid; i < NLEV*100; i += C) Pk[i/100][i%100] = g_P[b][i/100][i%100];
    __syncthreads();

    // upsweep: right += P[d] * left   (left = earlier 2^d chunks)
    for (int d = 0; d < NLEV; d++) {
        int nact = C >> (d + 1);
        if (tid < nact) {
            int i = ((tid + 1) << (d + 1)) - 1;
            int j = i - (1 << d);
            float acc[10];
            #pragma unroll
            for (int r = 0; r < 10; r++) acc[r] = sd[i][r];
            #pragma unroll
            for (int k = 0; k < 10; k++) {
                float s = sd[j][k];
                #pragma unroll
                for (int r = 0; r < 10; r++) acc[r] = fmaf(Pk[d][r*10 + k], s, acc[r]);
            }
            #pragma unroll
            for (int r = 0; r < 10; r++) sd[i][r] = acc[r];
        }
        __syncthreads();
    }

    if (tid == 0) {
        #pragma unroll
        for (int r = 0; r < 10; r++) sd[C-1][r] = 0.f;
    }
    __syncthreads();

    // downsweep: t=left; left=parent; right = P[d]*parent + t
    for (int d = NLEV - 1; d >= 0; d--) {
        int nact = C >> (d + 1);
        if (tid < nact) {
            int i = ((tid + 1) << (d + 1)) - 1;
            int j = i - (1 << d);
            float tl[10], pr[10], acc[10];
            #pragma unroll
            for (int r = 0; r < 10; r++) { tl[r] = sd[j][r]; pr[r] = sd[i][r]; }
            #pragma unroll
            for (int r = 0; r < 10; r++) { sd[j][r] = pr[r]; acc[r] = tl[r]; }
            #pragma unroll
            for (int k = 0; k < 10; k++) {
                float s = pr[k];
                #pragma unroll
                for (int r = 0; r < 10; r++) acc[r] = fmaf(Pk[d][r*10 + k], s, acc[r]);
            }
            #pragma unroll
            for (int r = 0; r < 10; r++) sd[i][r] = acc[r];
        }
        __syncthreads();
    }

    #pragma unroll
    for (int r = 0; r < 10; r++) g_w[b][tid][r] = sd[tid][r];
}

// ---------------- phase 3: re-run chunks with true init state, write y ----------------
__global__ void __launch_bounds__(128) k_phase3(const float* __restrict__ x, float* __restrict__ y) {
    int t = blockIdx.x * blockDim.x + threadIdx.x;
    int b = t >> 10;
    int c = t & (C - 1);
    float cf[5][5];
    #pragma unroll
    for (int k = 0; k < 5; k++)
        #pragma unroll
        for (int i = 0; i < 5; i++) cf[k][i] = g_coef[b][k][i];
    float z1[5], z2[5];
    #pragma unroll
    for (int k = 0; k < 5; k++) { z1[k] = g_w[b][c][k]; z2[k] = g_w[b][c][5+k]; }
    const float4* xp = (const float4*)(x + (size_t)b*T + (size_t)c*LCH);
    float4*       yp = (float4*)      (y + (size_t)b*T + (size_t)c*LCH);
    #pragma unroll 4
    for (int i = 0; i < LCH/4; i++) {
        float4 v = __ldg(xp + i);
        float4 o;
        o.x = eq_step(cf, z1, z2, v.x);
        o.y = eq_step(cf, z1, z2, v.y);
        o.z = eq_step(cf, z1, z2, v.z);
        o.w = eq_step(cf, z1, z2, v.w);
        yp[i] = o;
    }
}

// ---------------- launch ----------------
extern "C" void kernel_launch(void* const* d_in, const int* in_sizes, int n_in,
                              void* d_out, int out_size) {
    // Robust input selection by element count: x has NB*T elements, cp has NB*15.
    const float* x  = nullptr;
    const float* cp = nullptr;
    for (int i = 0; i < n_in; i++) {
        if (in_sizes[i] == NB * T)       x  = (const float*)d_in[i];
        else if (in_sizes[i] == NB * 15) cp = (const float*)d_in[i];
    }
    if (!x)  x  = (const float*)d_in[0];
    if (!cp) cp = (const float*)d_in[n_in > 1 ? 1 : 0];

    float* out = (float*)d_out;
    float* sos_out = (out_size >= NB*T + NB*30) ? (out + (size_t)NB*T) : nullptr;

    k_setup <<<NB, 128>>>(cp, sos_out);
    k_phase1<<<(NB*C)/128, 128>>>(x);
    k_scan  <<<NB, C>>>();
    k_phase3<<<(NB*C)/128, 128>>>(x, out);
}

// round 6
// speedup vs baseline: 1.0044x; 1.0044x over previous
#include <cuda_runtime.h>

#define NB   32
#define T    131072
#define LCH  128
#define C    1024     // T / LCH
#define NSEC 5
#define NLEV 10       // log2(C)

// ---------------- scratch (device globals, no allocation) ----------------
__device__ float g_coef[NB][NSEC][5];      // B0,B1,B2,A1,A2 (normalized)
__device__ float g_P[NB][NLEV][100];       // A^(LCH*2^k), k=0..9 (double-computed)
__device__ float g_v[NB][C][10];           // zero-state chunk final states
__device__ float g_w[NB][C][10];           // true chunk initial states

__constant__ float c_lo[15] = {-12.f,  20.f, 0.1f, -12.f,   20.f, 0.1f,
                               -12.f, 200.f, 0.1f, -12.f, 2000.f, 0.1f,
                               -12.f,4000.f, 0.1f};
__constant__ float c_hi[15] = { 12.f,2000.f,10.f,  12.f,  200.f,10.f,
                                12.f,2000.f,10.f,  12.f,12000.f,10.f,
                                12.f,16000.f,10.f};

// ---------------- setup: coeffs + sos output + matrix powers (double) ----------------
__global__ void k_setup(const float* __restrict__ cp, float* __restrict__ sos_out) {
    int b = blockIdx.x, tid = threadIdx.x;
    __shared__ double sd[NSEC][5];
    __shared__ double Ma[100], Mb[100];

    if (tid < NSEC) {
        int k = tid;
        double pg = (double)c_lo[3*k+0] + (double)cp[b*15 + 3*k+0] * ((double)c_hi[3*k+0] - (double)c_lo[3*k+0]);
        double f0 = (double)c_lo[3*k+1] + (double)cp[b*15 + 3*k+1] * ((double)c_hi[3*k+1] - (double)c_lo[3*k+1]);
        double q  = (double)c_lo[3*k+2] + (double)cp[b*15 + 3*k+2] * ((double)c_hi[3*k+2] - (double)c_lo[3*k+2]);

        double A     = pow(10.0, pg / 40.0);
        double w0    = 2.0 * 3.14159265358979323846 * f0 / 44100.0;
        double alpha = sin(w0) / (2.0 * q);
        double cw    = cos(w0);
        double sA    = sqrt(A);
        double b0, b1, b2, a0, a1, a2;
        if (k == 0) {            // low shelf
            b0 = A*((A+1) - (A-1)*cw + 2*sA*alpha);
            b1 = 2*A*((A-1) - (A+1)*cw);
            b2 = A*((A+1) - (A-1)*cw - 2*sA*alpha);
            a0 = (A+1) + (A-1)*cw + 2*sA*alpha;
            a1 = -2*((A-1) + (A+1)*cw);
            a2 = (A+1) + (A-1)*cw - 2*sA*alpha;
        } else if (k == 4) {     // high shelf
            b0 = A*((A+1) + (A-1)*cw + 2*sA*alpha);
            b1 = -2*A*((A-1) + (A+1)*cw);
            b2 = A*((A+1) + (A-1)*cw - 2*sA*alpha);
            a0 = (A+1) - (A-1)*cw + 2*sA*alpha;
            a1 = 2*((A-1) - (A+1)*cw);
            a2 = (A+1) - (A-1)*cw - 2*sA*alpha;
        } else {                 // peaking
            b0 = 1 + alpha*A;  b1 = -2*cw;  b2 = 1 - alpha*A;
            a0 = 1 + alpha/A;  a1 = -2*cw;  a2 = 1 - alpha/A;
        }
        double B0 = b0/a0, B1 = b1/a0, B2 = b2/a0, A1 = a1/a0, A2 = a2/a0;
        sd[k][0]=B0; sd[k][1]=B1; sd[k][2]=B2; sd[k][3]=A1; sd[k][4]=A2;
        g_coef[b][k][0]=(float)B0; g_coef[b][k][1]=(float)B1; g_coef[b][k][2]=(float)B2;
        g_coef[b][k][3]=(float)A1; g_coef[b][k][4]=(float)A2;
        if (sos_out) {
            float* so = sos_out + b*30 + k*6;
            so[0]=(float)B0; so[1]=(float)B1; so[2]=(float)B2;
            so[3]=1.0f;      so[4]=(float)A1; so[5]=(float)A2;
        }
    }
    __syncthreads();

    // one-step state matrix A by basis simulation (double): column j = step(e_j, x=0)
    if (tid < 10) {
        double z1[5] = {0,0,0,0,0}, z2[5] = {0,0,0,0,0};
        if (tid < 5) z1[tid] = 1.0; else z2[tid-5] = 1.0;
        double s = 0.0;
        #pragma unroll
        for (int k = 0; k < 5; k++) {
            double y   = fma(sd[k][0], s, z1[k]);
            double nz1 = fma(sd[k][1], s, fma(-sd[k][3], y, z2[k]));
            double nz2 = fma(sd[k][2], s, -sd[k][4]*y);
            z1[k] = nz1; z2[k] = nz2; s = y;
        }
        #pragma unroll
        for (int r = 0; r < 5; r++) { Ma[r*10+tid] = z1[r]; Ma[(5+r)*10+tid] = z2[r]; }
    }
    __syncthreads();

    // 16 squarings in double: after sq squarings M = A^(2^sq).
    // LCH = 128 = 2^7 -> scan levels are A^(2^(7+d)), d=0..9 -> store sq=7..16.
    double* cur = Ma; double* nxt = Mb;
    for (int sq = 1; sq <= 16; sq++) {
        double acc = 0.0;
        if (tid < 100) {
            int r = tid / 10, c2 = tid % 10;
            #pragma unroll
            for (int k = 0; k < 10; k++)
                acc = fma(cur[r*10+k], cur[k*10+c2], acc);
        }
        __syncthreads();
        if (tid < 100) nxt[tid] = acc;
        __syncthreads();
        double* t2 = cur; cur = nxt; nxt = t2;
        if (sq >= 7 && tid < 100) g_P[b][sq-7][tid] = (float)cur[tid];
    }
}

// ---------------- cascade step ----------------
__device__ __forceinline__ float eq_step(const float cf[5][5], float z1[5], float z2[5], float s) {
    #pragma unroll
    for (int k = 0; k < 5; k++) {
        float y   = fmaf(cf[k][0], s, z1[k]);
        float nz1 = fmaf(cf[k][1], s, fmaf(-cf[k][3], y, z2[k]));
        z2[k]     = fmaf(cf[k][2], s, -cf[k][4]*y);
        z1[k] = nz1; s = y;
    }
    return s;
}

// ---------------- phase 1: zero-state chunk final states ----------------
__global__ void __launch_bounds__(128) k_phase1(const float* __restrict__ x) {
    int t = blockIdx.x * blockDim.x + threadIdx.x;
    int b = t >> 10;           // / C
    int c = t & (C - 1);
    float cf[5][5];
    #pragma unroll
    for (int k = 0; k < 5; k++)
        #pragma unroll
        for (int i = 0; i < 5; i++) cf[k][i] = g_coef[b][k][i];
    float z1[5] = {0,0,0,0,0}, z2[5] = {0,0,0,0,0};
    const float4* xp = (const float4*)(x + (size_t)b*T + (size_t)c*LCH);
    #pragma unroll 4
    for (int i = 0; i < LCH/4; i++) {
        float4 v = __ldg(xp + i);
        eq_step(cf, z1, z2, v.x);
        eq_step(cf, z1, z2, v.y);
        eq_step(cf, z1, z2, v.z);
        eq_step(cf, z1, z2, v.w);
    }
    #pragma unroll
    for (int k = 0; k < 5; k++) { g_v[b][c][k] = z1[k]; g_v[b][c][5+k] = z2[k]; }
}

// ---------------- inter-chunk Blelloch scan (one CTA per batch, work-efficient) ----------------
__global__ void __launch_bounds__(C) k_scan() {
    int b = blockIdx.x;
    int tid = threadIdx.x;     // C threads
    __shared__ float sd[C][11];      // padded: 2-way max bank conflicts
    __shared__ float Pk[NLEV][100];

    #pragma unroll
    for (int r = 0; r < 10; r++) sd[tid][r] = g_v[b][tid][r];
    for (int i = tid; i < NLEV*100; i += C) Pk[i/100][i%100] = g_P[b][i/100][i%100];
    __syncthreads();

    // upsweep: right += P[d] * left   (left = earlier 2^d chunks)
    for (int d = 0; d < NLEV; d++) {
        int nact = C >> (d + 1);
        if (tid < nact) {
            int i = ((tid + 1) << (d + 1)) - 1;
            int j = i - (1 << d);
            float acc[10];
            #pragma unroll
            for (int r = 0; r < 10; r++) acc[r] = sd[i][r];
            #pragma unroll
            for (int k = 0; k < 10; k++) {
                float s = sd[j][k];
                #pragma unroll
                for (int r = 0; r < 10; r++) acc[r] = fmaf(Pk[d][r*10 + k], s, acc[r]);
            }
            #pragma unroll
            for (int r = 0; r < 10; r++) sd[i][r] = acc[r];
        }
        __syncthreads();
    }

    if (tid == 0) {
        #pragma unroll
        for (int r = 0; r < 10; r++) sd[C-1][r] = 0.f;
    }
    __syncthreads();

    // downsweep: t=left; left=parent; right = P[d]*parent + t
    for (int d = NLEV - 1; d >= 0; d--) {
        int nact = C >> (d + 1);
        if (tid < nact) {
            int i = ((tid + 1) << (d + 1)) - 1;
            int j = i - (1 << d);
            float tl[10], pr[10], acc[10];
            #pragma unroll
            for (int r = 0; r < 10; r++) { tl[r] = sd[j][r]; pr[r] = sd[i][r]; }
            #pragma unroll
            for (int r = 0; r < 10; r++) { sd[j][r] = pr[r]; acc[r] = tl[r]; }
            #pragma unroll
            for (int k = 0; k < 10; k++) {
                float s = pr[k];
                #pragma unroll
                for (int r = 0; r < 10; r++) acc[r] = fmaf(Pk[d][r*10 + k], s, acc[r]);
            }
            #pragma unroll
            for (int r = 0; r < 10; r++) sd[i][r] = acc[r];
        }
        __syncthreads();
    }

    #pragma unroll
    for (int r = 0; r < 10; r++) g_w[b][tid][r] = sd[tid][r];
}

// ---------------- phase 3: re-run chunks with true init state, write y ----------------
__global__ void __launch_bounds__(128) k_phase3(const float* __restrict__ x, float* __restrict__ y) {
    int t = blockIdx.x * blockDim.x + threadIdx.x;
    int b = t >> 10;
    int c = t & (C - 1);
    float cf[5][5];
    #pragma unroll
    for (int k = 0; k < 5; k++)
        #pragma unroll
        for (int i = 0; i < 5; i++) cf[k][i] = g_coef[b][k][i];
    float z1[5], z2[5];
    #pragma unroll
    for (int k = 0; k < 5; k++) { z1[k] = g_w[b][c][k]; z2[k] = g_w[b][c][5+k]; }
    const float4* xp = (const float4*)(x + (size_t)b*T + (size_t)c*LCH);
    float4*       yp = (float4*)      (y + (size_t)b*T + (size_t)c*LCH);
    #pragma unroll 4
    for (int i = 0; i < LCH/4; i++) {
        float4 v = __ldg(xp + i);
        float4 o;
        o.x = eq_step(cf, z1, z2, v.x);
        o.y = eq_step(cf, z1, z2, v.y);
        o.z = eq_step(cf, z1, z2, v.z);
        o.w = eq_step(cf, z1, z2, v.w);
        yp[i] = o;
    }
}

// ---------------- launch ----------------
extern "C" void kernel_launch(void* const* d_in, const int* in_sizes, int n_in,
                              void* d_out, int out_size) {
    // Robust input selection by element count: x has NB*T elements, cp has NB*15.
    const float* x  = nullptr;
    const float* cp = nullptr;
    for (int i = 0; i < n_in; i++) {
        if (in_sizes[i] == NB * T)       x  = (const float*)d_in[i];
        else if (in_sizes[i] == NB * 15) cp = (const float*)d_in[i];
    }
    if (!x)  x  = (const float*)d_in[0];
    if (!cp) cp = (const float*)d_in[n_in > 1 ? 1 : 0];

    float* out = (float*)d_out;
    float* sos_out = (out_size >= NB*T + NB*30) ? (out + (size_t)NB*T) : nullptr;

    k_setup <<<NB, 128>>>(cp, sos_out);
    k_phase1<<<(NB*C)/128, 128>>>(x);
    k_scan  <<<NB, C>>>();
    k_phase3<<<(NB*C)/128, 128>>>(x, out);
}